// round 9
// baseline (speedup 1.0000x reference)
#include <cuda_runtime.h>

#define XS 8192

// Scratch (allocation-free)
__device__ float g_Tpart[16 * 16 * 2 * 1024];   // [k][e][pq][s][o]
__device__ unsigned int g_cnt[16];              // per-k counters (16 producers each)

static __device__ __forceinline__ unsigned int ld_acq(const unsigned int* p) {
    unsigned int v;
    asm volatile("ld.acquire.gpu.u32 %0, [%1];" : "=r"(v) : "l"(p));
    return v;
}
static __device__ __forceinline__ unsigned int atom_add_rel(unsigned int* p, unsigned int v) {
    unsigned int o;
    asm volatile("atom.release.gpu.add.u32 %0, [%1], %2;"
                 : "=r"(o) : "l"(p), "r"(v) : "memory");
    return o;
}

__global__ void __launch_bounds__(256, 2) fused_kernel(
    const float* __restrict__ x,
    const float* __restrict__ w_diag,
    const float* __restrict__ w_off,
    const float* __restrict__ b1,
    const int*   __restrict__ perm,
    float*       __restrict__ out)
{
    __shared__ float4 Wp4[288], Wm4[288], Sp4[288], Sm4[288];  // rows of 9 f4 (pad)
    __shared__ float4 wdsh4[264];     // [iq*33 + o]
    __shared__ float  tshF[128];      // [p][sL][o]
    __shared__ float  bsh[32];

    const int b = blockIdx.x, t = threadIdx.x;
    const int k = b >> 4, e = b & 15;   // producer: B-pair e; consumer: samples {2e,2e+1}

    if (t < 32) bsh[t] = __ldg(&b1[t]);

    // consumer-role indices (early)
    const int aa = (t >> 3) & 15, ogc = t & 7, sLc = t >> 7;
    const int n2 = __ldg(&perm[k * 16 + aa]);

    // ---- W prefetch: (a_i, b_i) = w_off[c][k][2e], [2e+1] as float2 ----
    const float2* woff2 = (const float2*)w_off;
    float2 wreg[4];
#pragma unroll
    for (int j = 0; j < 4; j++)
        wreg[j] = __ldg(&woff2[(j * 256 + t) * 256 + k * 16 + e]);

    // ---- w_diag column k -> smem [iq][o] ----
    {
        float* wdf = (float*)wdsh4;
#pragma unroll
        for (int j = 0; j < 4; j++) {
            int c = j * 256 + t, o = c >> 5, i = c & 31;
            wdf[((i >> 2) * 33 + o) * 4 + (i & 3)] = __ldg(&w_diag[c * 16 + k]);
        }
    }

    // ================= phase A: gather 16 rows, S± for pair e ===============
    {
        const int sA = t >> 3, iqA = t & 7;
        const float4* x4 = (const float4*)x;
        float4 a0 = make_float4(0.f, 0.f, 0.f, 0.f);
        float4 a1 = make_float4(0.f, 0.f, 0.f, 0.f);
#pragma unroll
        for (int r = 0; r < 8; r++) {
            int n = __ldg(&perm[16 * e + r]);
            float4 v = __ldg(&x4[sA * 2048 + n * 8 + iqA]);
            a0.x += v.x; a0.y += v.y; a0.z += v.z; a0.w += v.w;
        }
#pragma unroll
        for (int r = 0; r < 8; r++) {
            int n = __ldg(&perm[16 * e + 8 + r]);
            float4 v = __ldg(&x4[sA * 2048 + n * 8 + iqA]);
            a1.x += v.x; a1.y += v.y; a1.z += v.z; a1.w += v.w;
        }
        float4 p, q;
        p.x = a0.x + a1.x; p.y = a0.y + a1.y; p.z = a0.z + a1.z; p.w = a0.w + a1.w;
        q.x = a0.x - a1.x; q.y = a0.y - a1.y; q.z = a0.z - a1.z; q.w = a0.w - a1.w;
        Sp4[sA * 9 + iqA] = p;
        Sm4[sA * 9 + iqA] = q;
    }

    // ---- W± -> smem ----
    {
        float* Wpf = (float*)Wp4;
        float* Wmf = (float*)Wm4;
#pragma unroll
        for (int j = 0; j < 4; j++) {
            int c = j * 256 + t, o = c >> 5, i = c & 31;
            Wpf[o * 36 + i] = wreg[j].x + wreg[j].y;
            Wmf[o * 36 + i] = wreg[j].x - wreg[j].y;
        }
    }
    __syncthreads();

    // ================= phase B: contraction (K=32, one m-pair) ==============
    {
        const int ih = t & 1, og = (t >> 1) & 7, sb = (t >> 4) & 7, pq = t >> 7;
        const float4* Wb = pq ? Wm4 : Wp4;
        const float4* Sb = pq ? Sm4 : Sp4;
        float acc[4][4];
#pragma unroll
        for (int j = 0; j < 16; j++) ((float*)acc)[j] = 0.f;
#pragma unroll
        for (int j = 0; j < 4; j++) {
            int iq = ih * 4 + j;
            float4 sv[4], wv[4];
#pragma unroll
            for (int ss = 0; ss < 4; ss++) sv[ss] = Sb[(sb + 8 * ss) * 9 + iq];
#pragma unroll
            for (int oo = 0; oo < 4; oo++) wv[oo] = Wb[(og + 8 * oo) * 9 + iq];
#pragma unroll
            for (int ss = 0; ss < 4; ss++)
#pragma unroll
                for (int oo = 0; oo < 4; oo++)
                    acc[ss][oo] += wv[oo].x * sv[ss].x + wv[oo].y * sv[ss].y
                                 + wv[oo].z * sv[ss].z + wv[oo].w * sv[ss].w;
        }
        // reduce over ih via shfl (pairs t, t^1)
#pragma unroll
        for (int u = 0; u < 16; u++) {
            float v = ((float*)acc)[u];
            ((float*)acc)[u] = v + __shfl_xor_sync(0xffffffffu, v, 1);
        }
        if (ih == 0) {
            float* Td = g_Tpart + ((k * 16 + e) * 2 + pq) * 1024;
#pragma unroll
            for (int ss = 0; ss < 4; ss++)
#pragma unroll
                for (int oo = 0; oo < 4; oo++)
                    Td[(sb + 8 * ss) * 32 + og + 8 * oo] = acc[ss][oo];
        }
    }

    // ---- release; overlap diag GEMM with other producers -------------------
    __syncthreads();
    unsigned int tgt = 0;
    if (t == 0) {
        unsigned int my = atom_add_rel(&g_cnt[k], 1u);
        tgt = ((my >> 4) + 1u) << 4;            // 16 producers per k
    }

    float4 xr[8];
    {
        const float4* xrow = (const float4*)(x + (2 * e + sLc) * XS + n2 * 32);
#pragma unroll
        for (int iq = 0; iq < 8; iq++) xr[iq] = __ldg(&xrow[iq]);
    }
    float accd[4];
#pragma unroll
    for (int oo = 0; oo < 4; oo++) accd[oo] = bsh[ogc + 8 * oo];
#pragma unroll
    for (int iq = 0; iq < 8; iq++) {
        float4 xv = xr[iq];
#pragma unroll
        for (int oo = 0; oo < 4; oo++) {
            float4 wv = wdsh4[iq * 33 + ogc + 8 * oo];
            accd[oo] += wv.x * xv.x + wv.y * xv.y + wv.z * xv.z + wv.w * xv.w;
        }
    }

    if (t == 0) { while (ld_acq(&g_cnt[k]) < tgt) {} }
    __syncthreads();

    // ---- T reduce (one warp, MLP 16) + Karatsuba combine via shfl ----------
    if (t < 32) {
        int pqr = t >> 4, sLr = (t >> 3) & 1, oq = t & 7;
        const float4* Tp4 = (const float4*)g_Tpart;
        float4 A = make_float4(0.f, 0.f, 0.f, 0.f);
#pragma unroll
        for (int e2 = 0; e2 < 16; e2++) {
            float4 v = __ldcg(&Tp4[((k * 16 + e2) * 2 + pqr) * 256
                                   + (2 * e + sLr) * 8 + oq]);
            A.x += v.x; A.y += v.y; A.z += v.z; A.w += v.w;
        }
        float4 B;
        B.x = __shfl_xor_sync(0xffffffffu, A.x, 16);
        B.y = __shfl_xor_sync(0xffffffffu, A.y, 16);
        B.z = __shfl_xor_sync(0xffffffffu, A.z, 16);
        B.w = __shfl_xor_sync(0xffffffffu, A.w, 16);
        const float cs = 1.0f / 512.0f;
        float4 T;
        if (pqr == 0) {      // holds P, partner Q : T0 = (P+Q)/512
            T.x = (A.x + B.x) * cs; T.y = (A.y + B.y) * cs;
            T.z = (A.z + B.z) * cs; T.w = (A.w + B.w) * cs;
        } else {             // holds Q, partner P : T1 = (P−Q)/512
            T.x = (B.x - A.x) * cs; T.y = (B.y - A.y) * cs;
            T.z = (B.z - A.z) * cs; T.w = (B.w - A.w) * cs;
        }
        ((float4*)tshF)[pqr * 16 + sLr * 8 + oq] = T;
    }
    __syncthreads();

    // ---- add T term + store -------------------------------------------------
    const int pa = aa >> 3;
    float* orow = out + (2 * e + sLc) * XS + n2 * 32;
#pragma unroll
    for (int oo = 0; oo < 4; oo++)
        orow[ogc + 8 * oo] = accd[oo] + tshF[pa * 64 + sLc * 32 + ogc + 8 * oo];
}

// ---------------------------------------------------------------------------
extern "C" void kernel_launch(void* const* d_in, const int* in_sizes, int n_in,
                              void* d_out, int out_size)
{
    const float* x      = (const float*)d_in[0];
    const float* w_diag = (const float*)d_in[1];
    const float* w_off  = (const float*)d_in[2];
    const float* b1     = (const float*)d_in[3];
    const int*   perm   = (const int*)d_in[4];
    float* out = (float*)d_out;

    fused_kernel<<<256, 256>>>(x, w_diag, w_off, b1, perm, out);
}